// round 4
// baseline (speedup 1.0000x reference)
#include <cuda_runtime.h>

#define NJ   24
#define HIDN 7
#define FT   6
#define TPB  128          // threads per block
#define TILE 256          // samples per block (pair rows t and t+128)
#define ROWF 64           // staged floats per sample row (16 chunks of 4; 48 valid + pad)

typedef unsigned long long u64;

__device__ __forceinline__ u64 pack2(float lo, float hi) {
    u64 r;
    asm("mov.b64 %0, {%1, %2};" : "=l"(r) : "f"(lo), "f"(hi));
    return r;
}
__device__ __forceinline__ void unpack2(u64 v, float& lo, float& hi) {
    asm("mov.b64 {%0, %1}, %2;" : "=f"(lo), "=f"(hi) : "l"(v));
}
// packed dual-sample FMA: d = a*b + c on both 32-bit halves (Blackwell FFMA2 path)
__device__ __forceinline__ u64 ffma2(u64 a, u64 b, u64 c) {
    u64 d;
    asm("fma.rn.f32x2 %0, %1, %2, %3;" : "=l"(d) : "l"(a), "l"(b), "l"(c));
    return d;
}

__global__ __launch_bounds__(TPB, 2)
void se1d_kernel(const float* __restrict__ x,
                 const float* __restrict__ W1,
                 const float* __restrict__ b1,
                 const float* __restrict__ W2,
                 const float* __restrict__ b2,
                 float* __restrict__ out,
                 int B)
{
    // skeleton parents; topo order is identity (parent[i] < i for all i)
    constexpr int PAR[NJ] = {-1,0,0,0,1,2,3,4,5,6,7,8,9,9,9,12,13,14,16,17,18,19,20,21};

    extern __shared__ char smem[];
    float* stage = reinterpret_cast<float*>(smem);                  // TILE*ROWF floats = 64 KB
    u64* sW1 = reinterpret_cast<u64*>(smem + TILE * ROWF * 4);      // duplicated {w,w}
    u64* sB1 = sW1 + NJ * HIDN * HIDN;   // 1176
    u64* sB2 = sB1 + NJ * HIDN;          // +168
    u64* sW2 = sB2 + NJ * FT;            // +144
    // sW2 spans NJ*FT*HIDN = 1008 entries

    const int t    = threadIdx.x;
    const int tile = blockIdx.x * TILE;

    // ---- cooperative weight load, duplicated into f32x2 lanes ----
    for (int i = t; i < NJ * HIDN * HIDN; i += TPB) { float w = W1[i]; sW1[i] = pack2(w, w); }
    for (int i = t; i < NJ * HIDN;        i += TPB) { float w = b1[i]; sB1[i] = pack2(w, w); }
    for (int i = t; i < NJ * FT * HIDN;   i += TPB) { float w = W2[i]; sW2[i] = pack2(w, w); }
    for (int i = t; i < NJ * FT;          i += TPB) { float w = b2[i]; sB2[i] = pack2(w, w); }

    // ---- load the pair of input rows (rows are 96 B, float4-aligned) ----
    const int r0 = tile + t;
    const int r1 = tile + TPB + t;

    float a0[NJ], a1[NJ];
    #pragma unroll
    for (int k = 0; k < NJ; k++) { a0[k] = 0.f; a1[k] = 0.f; }
    if (r0 < B) {
        const float4* p = reinterpret_cast<const float4*>(x + (size_t)r0 * NJ);
        #pragma unroll
        for (int q = 0; q < 6; q++) {
            float4 v = p[q];
            a0[4*q] = v.x; a0[4*q+1] = v.y; a0[4*q+2] = v.z; a0[4*q+3] = v.w;
        }
    }
    if (r1 < B) {
        const float4* p = reinterpret_cast<const float4*>(x + (size_t)r1 * NJ);
        #pragma unroll
        for (int q = 0; q < 6; q++) {
            float4 v = p[q];
            a1[4*q] = v.x; a1[4*q+1] = v.y; a1[4*q+2] = v.z; a1[4*q+3] = v.w;
        }
    }
    u64 xp[NJ];
    #pragma unroll
    for (int k = 0; k < NJ; k++) xp[k] = pack2(a0[k], a1[k]);

    __syncthreads();   // weights ready

    float4* out4 = reinterpret_cast<float4*>(out);
    u64 feat[NJ][FT];  // fully unrolled; ptxas liveness keeps only live features (<=4 joints)
    const int sw = t & 7;

    #pragma unroll
    for (int j = 0; j < NJ; j++) {
        const int p = PAR[j];

        // h = relu(inp @ W1[j]^T + b1[j]);  inp = [x_j, parent_feat]
        u64 h[HIDN];
        #pragma unroll
        for (int r = 0; r < HIDN; r++) {
            u64 acc = sB1[j * HIDN + r];
            acc = ffma2(xp[j], sW1[j * 49 + r * HIDN + 0], acc);
            if (p >= 0) {
                #pragma unroll
                for (int c = 1; c < HIDN; c++)
                    acc = ffma2(feat[p][c - 1], sW1[j * 49 + r * HIDN + c], acc);
            }
            float ha, hb; unpack2(acc, ha, hb);
            h[r] = pack2(fmaxf(ha, 0.f), fmaxf(hb, 0.f));
        }

        // o = relu(h @ W2[j]^T + b2[j])
        float olo[FT], ohi[FT];
        #pragma unroll
        for (int r = 0; r < FT; r++) {
            u64 acc = sB2[j * FT + r];
            #pragma unroll
            for (int c = 0; c < HIDN; c++)
                acc = ffma2(h[c], sW2[j * 42 + r * HIDN + c], acc);
            float oa, ob; unpack2(acc, oa, ob);
            oa = fmaxf(oa, 0.f); ob = fmaxf(ob, 0.f);
            olo[r] = oa; ohi[r] = ob;
            feat[j][r] = pack2(oa, ob);
        }

        // stage the 6 outputs for both samples (XOR-swizzled 16B chunks)
        {
            const int cb = (j & 7) * FT;            // phase-local channel base (0..42)
            #pragma unroll
            for (int k2 = 0; k2 < 3; k2++) {
                const int e     = cb + 2 * k2;      // compile-time
                const int chunk = e >> 2;
                const int off   = e & 3;
                float2* p0 = reinterpret_cast<float2*>(
                    &stage[t * ROWF + ((chunk ^ sw) << 2) + off]);
                *p0 = make_float2(olo[2*k2], olo[2*k2 + 1]);
                float2* p1 = reinterpret_cast<float2*>(
                    &stage[(t + TPB) * ROWF + ((chunk ^ sw) << 2) + off]);
                *p1 = make_float2(ohi[2*k2], ohi[2*k2 + 1]);
            }
        }

        // every 8 joints: flush 48 staged channels with coalesced STG.128
        if ((j & 7) == 7) {
            const int ph = j >> 3;
            __syncthreads();
            #pragma unroll
            for (int i = 0; i < 24; i++) {          // TILE*12 float4 / TPB threads
                const int kk = t + i * TPB;
                const int s  = kk / 12;
                const int c4 = kk % 12;
                float4 v = *reinterpret_cast<const float4*>(
                    &stage[s * ROWF + ((c4 ^ (s & 7)) << 2)]);
                const int gr = tile + s;
                if (gr < B)
                    out4[(size_t)gr * 36 + ph * 12 + c4] = v;
            }
            __syncthreads();
        }
    }
}

extern "C" void kernel_launch(void* const* d_in, const int* in_sizes, int n_in,
                              void* d_out, int out_size)
{
    const float* x  = (const float*)d_in[0];
    const float* W1 = (const float*)d_in[1];
    const float* b1 = (const float*)d_in[2];
    const float* W2 = (const float*)d_in[3];
    const float* b2 = (const float*)d_in[4];
    float* out = (float*)d_out;

    const int B = in_sizes[0] / NJ;
    const int blocks = (B + TILE - 1) / TILE;
    const size_t shm = (size_t)TILE * ROWF * 4                    // staging: 65536 B
                     + (size_t)NJ * (49 + 7 + 42 + 6) * 8;        // weights: 19968 B

    cudaFuncSetAttribute(se1d_kernel, cudaFuncAttributeMaxDynamicSharedMemorySize, (int)shm);
    se1d_kernel<<<blocks, TPB, shm>>>(x, W1, b1, W2, b2, out, B);
}

// round 8
// speedup vs baseline: 1.0429x; 1.0429x over previous
#include <cuda_runtime.h>

#define NJ   24
#define TPB  128          // threads per block
#define TILE 256          // samples per block (pair rows t and t+128)
#define ROWF 32           // staged floats per row (8 chunks of 4: 24 valid + 8 pad)

typedef unsigned long long u64;

__device__ __forceinline__ u64 pack2(float lo, float hi) {
    u64 r;
    asm("mov.b64 %0, {%1, %2};" : "=l"(r) : "f"(lo), "f"(hi));
    return r;
}
__device__ __forceinline__ void unpack2(u64 v, float& lo, float& hi) {
    asm("mov.b64 {%0, %1}, %2;" : "=f"(lo), "=f"(hi) : "l"(v));
}
// packed dual-sample FMA on both 32-bit halves (Blackwell FFMA2 path)
__device__ __forceinline__ u64 ffma2(u64 a, u64 b, u64 c) {
    u64 d;
    asm("fma.rn.f32x2 %0, %1, %2, %3;" : "=l"(d) : "l"(a), "l"(b), "l"(c));
    return d;
}

__global__ __launch_bounds__(TPB, 4)
void se1d_kernel(const float* __restrict__ x,
                 const float* __restrict__ W1,
                 const float* __restrict__ b1,
                 const float* __restrict__ W2,
                 const float* __restrict__ b2,
                 float* __restrict__ out,
                 int B)
{
    // skeleton parents; topo order is identity (parent[i] < i for all i)
    constexpr int PAR[NJ] = {-1,0,0,0,1,2,3,4,5,6,7,8,9,9,9,12,13,14,16,17,18,19,20,21};

    extern __shared__ char smem[];
    float* stage = reinterpret_cast<float*>(smem);              // TILE*ROWF*4 = 32 KB
    u64* sW1 = reinterpret_cast<u64*>(smem + TILE * ROWF * 4);  // 24*7*8 u64: row = [w0..w6, b1]
    u64* sW2 = sW1 + NJ * 7 * 8;                                // 24*6*8 u64: row = [w0..w6, b2]
    // smem total = 32768 + (1344+1152)*8 = 52736 B  -> 4 blocks/SM

    const int t    = threadIdx.x;
    const int tile = blockIdx.x * TILE;

    // ---- cooperative weight load: pad each row to 8 u64 {w,w} with bias in slot 7 ----
    for (int i = t; i < NJ * 56; i += TPB) {
        int j = i / 56, rem = i % 56, r = rem >> 3, c = rem & 7;
        float v = (c < 7) ? W1[j * 49 + r * 7 + c] : b1[j * 7 + r];
        sW1[i] = pack2(v, v);
    }
    for (int i = t; i < NJ * 48; i += TPB) {
        int j = i / 48, rem = i % 48, r = rem >> 3, c = rem & 7;
        float v = (c < 7) ? W2[j * 42 + r * 7 + c] : b2[j * 6 + r];
        sW2[i] = pack2(v, v);
    }

    // ---- x prefetch: 1 float4 chunk (4 joints) ahead, per sample row ----
    const int r0 = tile + t;
    const int r1 = tile + TPB + t;
    const bool v0 = r0 < B, v1 = r1 < B;
    const float4* px0 = reinterpret_cast<const float4*>(x + (size_t)r0 * NJ);
    const float4* px1 = reinterpret_cast<const float4*>(x + (size_t)r1 * NJ);
    const float4 fz = make_float4(0.f, 0.f, 0.f, 0.f);
    float4 ca = v0 ? px0[0] : fz;
    float4 cb = v1 ? px1[0] : fz;
    float4 na = fz, nb = fz;

    __syncthreads();   // weights ready

    float4* out4 = reinterpret_cast<float4*>(out);
    u64 feat[NJ][6];   // fully unrolled; liveness keeps <=3 joints (~36 regs)
    const int sw = t & 7;

    #pragma unroll
    for (int j = 0; j < NJ; j++) {
        // issue next x chunk at the start of each 4-joint phase
        if ((j & 3) == 0) {
            const int q = (j >> 2) + 1;
            if (q < 6) { na = v0 ? px0[q] : fz; nb = v1 ? px1[q] : fz; }
        }
        // select this joint's x component (compile-time after unroll)
        const int cc = j & 3;
        float xa = (cc == 0) ? ca.x : (cc == 1) ? ca.y : (cc == 2) ? ca.z : ca.w;
        float xb = (cc == 0) ? cb.x : (cc == 1) ? cb.y : (cc == 2) ? cb.z : cb.w;
        const u64 xp = pack2(xa, xb);

        const int p = PAR[j];
        const u64* w1j = sW1 + j * 56;

        // h = relu([x_j, parent_feat] @ W1^T + b1): 4x LDS.128 per row
        u64 h[7];
        #pragma unroll
        for (int r = 0; r < 7; r++) {
            const ulonglong2* q4 = reinterpret_cast<const ulonglong2*>(w1j + r * 8);
            ulonglong2 q0 = q4[0], q1 = q4[1], q2 = q4[2], q3 = q4[3];
            u64 acc = q3.y;                      // bias
            acc = ffma2(xp, q0.x, acc);
            if (p >= 0) {
                acc = ffma2(feat[p][0], q0.y, acc);
                acc = ffma2(feat[p][1], q1.x, acc);
                acc = ffma2(feat[p][2], q1.y, acc);
                acc = ffma2(feat[p][3], q2.x, acc);
                acc = ffma2(feat[p][4], q2.y, acc);
                acc = ffma2(feat[p][5], q3.x, acc);
            }
            float ha, hb; unpack2(acc, ha, hb);
            h[r] = pack2(fmaxf(ha, 0.f), fmaxf(hb, 0.f));
        }

        // o = relu(h @ W2^T + b2)
        const u64* w2j = sW2 + j * 48;
        float olo[6], ohi[6];
        #pragma unroll
        for (int r = 0; r < 6; r++) {
            const ulonglong2* q4 = reinterpret_cast<const ulonglong2*>(w2j + r * 8);
            ulonglong2 q0 = q4[0], q1 = q4[1], q2 = q4[2], q3 = q4[3];
            u64 acc = q3.y;                      // bias
            acc = ffma2(h[0], q0.x, acc);
            acc = ffma2(h[1], q0.y, acc);
            acc = ffma2(h[2], q1.x, acc);
            acc = ffma2(h[3], q1.y, acc);
            acc = ffma2(h[4], q2.x, acc);
            acc = ffma2(h[5], q2.y, acc);
            acc = ffma2(h[6], q3.x, acc);
            float oa, ob; unpack2(acc, oa, ob);
            oa = fmaxf(oa, 0.f); ob = fmaxf(ob, 0.f);
            olo[r] = oa; ohi[r] = ob;
            feat[j][r] = pack2(oa, ob);
        }

        // stage the 6 outputs for both samples (XOR-swizzled 16B chunks)
        {
            const int cbs = (j & 3) * 6;         // phase-local channel base (0..18)
            #pragma unroll
            for (int k2 = 0; k2 < 3; k2++) {
                const int e     = cbs + 2 * k2;  // compile-time
                const int chunk = e >> 2;
                const int off   = e & 3;
                *reinterpret_cast<float2*>(
                    &stage[t * ROWF + ((chunk ^ sw) << 2) + off]) =
                    make_float2(olo[2 * k2], olo[2 * k2 + 1]);
                *reinterpret_cast<float2*>(
                    &stage[(t + TPB) * ROWF + ((chunk ^ sw) << 2) + off]) =
                    make_float2(ohi[2 * k2], ohi[2 * k2 + 1]);
            }
        }

        // every 4 joints: flush 24 staged channels with coalesced STG.128
        if ((j & 3) == 3) {
            const int ph = j >> 2;
            __syncthreads();
            #pragma unroll
            for (int i = 0; i < 12; i++) {       // TILE*6 float4 / TPB threads
                const int kk = t + i * TPB;
                const int s  = kk / 6;
                const int c4 = kk % 6;
                float4 v = *reinterpret_cast<const float4*>(
                    &stage[s * ROWF + ((c4 ^ (s & 7)) << 2)]);
                const int gr = tile + s;
                if (gr < B)
                    out4[(size_t)gr * 36 + ph * 6 + c4] = v;
            }
            __syncthreads();
            if (j + 1 < NJ) { ca = na; cb = nb; }   // rotate x prefetch
        }
    }
}

extern "C" void kernel_launch(void* const* d_in, const int* in_sizes, int n_in,
                              void* d_out, int out_size)
{
    const float* x  = (const float*)d_in[0];
    const float* W1 = (const float*)d_in[1];
    const float* b1 = (const float*)d_in[2];
    const float* W2 = (const float*)d_in[3];
    const float* b2 = (const float*)d_in[4];
    float* out = (float*)d_out;

    const int B = in_sizes[0] / NJ;
    const int blocks = (B + TILE - 1) / TILE;
    const size_t shm = (size_t)TILE * ROWF * 4          // staging: 32768 B
                     + (size_t)(NJ * 56 + NJ * 48) * 8; // weights: 19968 B

    cudaFuncSetAttribute(se1d_kernel, cudaFuncAttributeMaxDynamicSharedMemorySize, (int)shm);
    se1d_kernel<<<blocks, TPB, shm>>>(x, W1, b1, W2, b2, out, B);
}